// round 1
// baseline (speedup 1.0000x reference)
#include <cuda_runtime.h>
#include <math.h>

#define C 512
#define HWN 1024
#define CHW (C*HWN)

__device__ __align__(16) float d_G[1024];        // G[i*32+x], normalized 1D gaussian
__device__ float d_mean[C];
__device__ float d_scale[C];
__device__ __align__(16) float d_out32[CHW];
__device__ __align__(16) float d_sig[CHW];
__device__ __align__(16) float d_tmp[CHW];       // [c][i*32+y]
__device__ __align__(16) float d_cat[2*CHW];     // first half gus flat (p*512+c), second half csa
__device__ float d_attn[HWN*9];
__device__ __align__(16) float d_y[CHW];

// ---- Gaussian weights: normalized separable 1D row (double precision to match float64 ref) ----
__global__ void k_gauss() {
    int i = threadIdx.x; // 0..31
    double ev[32]; double s = 0.0;
    #pragma unroll
    for (int x = 0; x < 32; x++) {
        double dd = (double)(x - i);
        double e = exp(-dd * dd / 4.5);   // 2*v^2 = 4.5 ; 1/(2 pi v^2) cancels in normalization
        ev[x] = e; s += e;
    }
    #pragma unroll
    for (int x = 0; x < 32; x++) d_G[i*32 + x] = (float)(ev[x] / s);
}

// ---- channel means ----
__global__ void k_mean(const float* __restrict__ x) {
    int c = blockIdx.x, t = threadIdx.x;
    float s = 0.f;
    for (int p = t; p < HWN; p += 256) s += x[c*HWN + p];
    __shared__ float red[256];
    red[t] = s; __syncthreads();
    for (int off = 128; off > 0; off >>= 1) { if (t < off) red[t] += red[t+off]; __syncthreads(); }
    if (t == 0) d_mean[c] = red[0] * (1.f/1024.f);
}

// ---- SE: fc -> relu -> fc -> sigmoid ----
__global__ void k_se(const float* __restrict__ w1, const float* __restrict__ w2) {
    __shared__ float s[512], s1[32];
    int t = threadIdx.x;
    s[t] = d_mean[t];
    __syncthreads();
    if (t < 32) {
        float a = 0.f;
        for (int c = 0; c < 512; c++) a += w1[t*512 + c] * s[c];
        s1[t] = fmaxf(a, 0.f);
    }
    __syncthreads();
    float a = 0.f;
    #pragma unroll
    for (int j = 0; j < 32; j++) a += w2[t*32 + j] * s1[j];
    d_scale[t] = 1.f / (1.f + expf(-a));
}

// ---- out32 = x*scale, sig = sigmoid(out32) ----
__global__ void k_scale_sig(const float* __restrict__ x) {
    int idx = blockIdx.x * 256 + threadIdx.x;
    float v = x[idx] * d_scale[idx >> 10];
    d_out32[idx] = v;
    d_sig[idx] = 1.f / (1.f + expf(-v));
}

// ---- gaussian stage 1: tmp[c][i*32+y] = sum_x G[i,x]*out32[c, x*32+y] ----
__global__ void k_gauss1() {
    int c = blockIdx.x, t = threadIdx.x;
    __shared__ float sO[1024], sG[1024];
    #pragma unroll
    for (int j = 0; j < 4; j++) {
        sO[t + j*256] = d_out32[c*1024 + t + j*256];
        sG[t + j*256] = d_G[t + j*256];
    }
    __syncthreads();
    #pragma unroll
    for (int j = 0; j < 4; j++) {
        int e = t + j*256;
        int i = e >> 5, y = e & 31;
        float acc = 0.f;
        #pragma unroll
        for (int xx = 0; xx < 32; xx++) acc += sG[i*32 + xx] * sO[xx*32 + y];
        d_tmp[c*1024 + e] = acc;
    }
}

// ---- gaussian stage 2: cat[p*512+c] = sum_y G[k,y]*tmp[c][i*32+y] ----
__global__ void k_gauss2() {
    int p = blockIdx.x, c = threadIdx.x;
    int i = p >> 5, k = p & 31;
    __shared__ float gk[32];
    if (c < 32) gk[c] = d_G[k*32 + c];
    __syncthreads();
    const float4* tp = reinterpret_cast<const float4*>(d_tmp + (size_t)c*1024 + i*32);
    float acc = 0.f;
    #pragma unroll
    for (int q = 0; q < 8; q++) {
        float4 v = tp[q];
        acc += gk[q*4+0]*v.x + gk[q*4+1]*v.y + gk[q*4+2]*v.z + gk[q*4+3]*v.w;
    }
    d_cat[p*512 + c] = acc;
}

// ---- CSA scores + softmax: attn[p][9] ----
__global__ void k_score() {
    int h = blockIdx.x, t = threadIdx.x;
    int cc = t & 7, w = t >> 3;
    __shared__ float sS[768];        // [ci(8)][row(3)][w(32)]
    __shared__ float red[256*9];
    float acc[9];
    #pragma unroll
    for (int d = 0; d < 9; d++) acc[d] = 0.f;
    for (int c0 = 0; c0 < 512; c0 += 8) {
        __syncthreads();
        #pragma unroll
        for (int j = 0; j < 3; j++) {
            int l = t + j*256;
            int ci = l / 96, rem = l % 96;
            int row = rem >> 5, ww = rem & 31;
            int gh = h - 1 + row;
            float v = 0.f;
            if (gh >= 0 && gh < 32) v = d_sig[(c0+ci)*1024 + gh*32 + ww];
            sS[l] = v;
        }
        __syncthreads();
        float center = sS[cc*96 + 32 + w];
        #pragma unroll
        for (int di = 0; di < 3; di++) {
            #pragma unroll
            for (int dj = 0; dj < 3; dj++) {
                int nw = w + dj - 1;
                float v = (nw >= 0 && nw < 32) ? sS[cc*96 + di*32 + nw] : 0.f;
                acc[di*3+dj] += center * v;
            }
        }
    }
    #pragma unroll
    for (int d = 0; d < 9; d++) red[t*9 + d] = acc[d];
    __syncthreads();
    if (cc == 0) {
        float sc[9];
        #pragma unroll
        for (int d = 0; d < 9; d++) {
            float s = 0.f;
            #pragma unroll
            for (int q = 0; q < 8; q++) s += red[(w*8+q)*9 + d];
            sc[d] = s * (1.f/512.f);
        }
        float m = sc[0];
        #pragma unroll
        for (int d = 1; d < 9; d++) m = fmaxf(m, sc[d]);
        float e[9], ss = 0.f;
        #pragma unroll
        for (int d = 0; d < 9; d++) { e[d] = expf(sc[d]-m); ss += e[d]; }
        float inv = 1.f / ss;
        #pragma unroll
        for (int d = 0; d < 9; d++) d_attn[(h*32+w)*9 + d] = e[d]*inv;
    }
}

// ---- CSA apply: cat[CHW + p*512 + c] = sum_d attn[p][d]*raw_patch ----
__global__ void k_csa() {
    int h = blockIdx.y;
    int c0 = blockIdx.x * 8;
    int t = threadIdx.x;
    int cc = t & 7, w = t >> 3;
    __shared__ float sO[768];
    __shared__ float sA[288];
    #pragma unroll
    for (int j = 0; j < 3; j++) {
        int l = t + j*256;
        int ci = l / 96, rem = l % 96;
        int row = rem >> 5, ww = rem & 31;
        int gh = h - 1 + row;
        sO[l] = (gh >= 0 && gh < 32) ? d_out32[(c0+ci)*1024 + gh*32 + ww] : 0.f;
    }
    for (int l = t; l < 288; l += 256) sA[l] = d_attn[h*32*9 + l];
    __syncthreads();
    float acc = 0.f;
    #pragma unroll
    for (int di = 0; di < 3; di++) {
        #pragma unroll
        for (int dj = 0; dj < 3; dj++) {
            int nw = w + dj - 1;
            float v = (nw >= 0 && nw < 32) ? sO[cc*96 + di*32 + nw] : 0.f;
            acc += sA[w*9 + di*3 + dj] * v;
        }
    }
    d_cat[CHW + (h*32+w)*512 + c0 + cc] = acc;
}

// ---- GEMM: y[o, hw] = sum_i W[o,i]*cat[i*1024+hw]  (512 x 1024 x 1024) ----
__global__ void k_gemm(const float* __restrict__ Wd) {
    int n0 = blockIdx.x * 64;
    int m0 = blockIdx.y * 64;
    int t = threadIdx.x;
    __shared__ float As[16][64];
    __shared__ float Bs[16][64];
    int tx = t & 15, ty = t >> 4;
    float acc[4][4] = {};
    for (int k0 = 0; k0 < 1024; k0 += 16) {
        #pragma unroll
        for (int j = 0; j < 4; j++) {
            int l = t + j*256;
            int o = l >> 4, kk = l & 15;
            As[kk][o] = Wd[(m0+o)*1024 + k0 + kk];
        }
        #pragma unroll
        for (int j = 0; j < 4; j++) {
            int l = t + j*256;
            int kk = l >> 6, nn = l & 63;
            Bs[kk][nn] = d_cat[(k0+kk)*1024 + n0 + nn];
        }
        __syncthreads();
        #pragma unroll
        for (int kk = 0; kk < 16; kk++) {
            float a[4], b[4];
            #pragma unroll
            for (int u = 0; u < 4; u++) a[u] = As[kk][ty*4+u];
            #pragma unroll
            for (int u = 0; u < 4; u++) b[u] = Bs[kk][tx*4+u];
            #pragma unroll
            for (int u = 0; u < 4; u++)
                #pragma unroll
                for (int v = 0; v < 4; v++) acc[u][v] += a[u]*b[v];
        }
        __syncthreads();
    }
    #pragma unroll
    for (int u = 0; u < 4; u++)
        #pragma unroll
        for (int v = 0; v < 4; v++)
            d_y[(m0+ty*4+u)*1024 + n0 + tx*4 + v] = acc[u][v];
}

// ---- instance norm (two-pass, biased var) + leaky relu(0.2) ----
__global__ void k_inorm(float* __restrict__ out) {
    int o = blockIdx.x, t = threadIdx.x;
    __shared__ float sv[1024];
    __shared__ float red[256];
    #pragma unroll
    for (int j = 0; j < 4; j++) sv[t + j*256] = d_y[o*1024 + t + j*256];
    __syncthreads();
    float s = 0.f;
    #pragma unroll
    for (int j = 0; j < 4; j++) s += sv[t + j*256];
    red[t] = s; __syncthreads();
    for (int off = 128; off > 0; off >>= 1) { if (t < off) red[t] += red[t+off]; __syncthreads(); }
    float mu = red[0] * (1.f/1024.f);
    __syncthreads();
    float q = 0.f;
    #pragma unroll
    for (int j = 0; j < 4; j++) { float d = sv[t + j*256] - mu; q += d*d; }
    red[t] = q; __syncthreads();
    for (int off = 128; off > 0; off >>= 1) { if (t < off) red[t] += red[t+off]; __syncthreads(); }
    float var = red[0] * (1.f/1024.f);
    float rs = rsqrtf(var + 1e-5f);
    #pragma unroll
    for (int j = 0; j < 4; j++) {
        float v = (sv[t + j*256] - mu) * rs;
        out[o*1024 + t + j*256] = v >= 0.f ? v : 0.2f*v;
    }
}

extern "C" void kernel_launch(void* const* d_in, const int* in_sizes, int n_in,
                              void* d_out, int out_size) {
    const float* x  = (const float*)d_in[0];
    const float* w1 = (const float*)d_in[1];
    const float* w2 = (const float*)d_in[2];
    const float* wd = (const float*)d_in[3];
    float* out = (float*)d_out;

    k_gauss<<<1, 32>>>();
    k_mean<<<512, 256>>>(x);
    k_se<<<1, 512>>>(w1, w2);
    k_scale_sig<<<2048, 256>>>(x);
    k_gauss1<<<512, 256>>>();
    k_gauss2<<<1024, 512>>>();
    k_score<<<32, 256>>>();
    k_csa<<<dim3(64, 32), 256>>>();
    k_gemm<<<dim3(16, 8), 256>>>(wd);
    k_inorm<<<512, 256>>>(out);
}

// round 2
// speedup vs baseline: 1.6128x; 1.6128x over previous
#include <cuda_runtime.h>
#include <math.h>

#define C 512
#define HWN 1024
#define CHW (C*HWN)

__device__ __align__(16) float d_G[1024];        // G[i*32+x], normalized 1D gaussian
__device__ float d_mean[C];
__device__ float d_scale[C];
__device__ __align__(16) float d_out32[CHW];     // [c][hw]
__device__ __align__(16) float d_out32T[CHW];    // [hw][c]
__device__ __align__(16) float d_sigT[CHW];      // [hw][c]
__device__ __align__(16) float d_tmp[CHW];       // [c][i*32+y]
__device__ __align__(16) float d_cat[2*CHW];     // gus flat (p*512+c) ; csa flat
__device__ __align__(16) float d_y[CHW];

// ---- Gaussian weights: normalized separable 1D row ----
__global__ void k_gauss() {
    int i = threadIdx.x; // 0..31
    double ev[32]; double s = 0.0;
    #pragma unroll
    for (int x = 0; x < 32; x++) {
        double dd = (double)(x - i);
        double e = exp(-dd * dd / 4.5);
        ev[x] = e; s += e;
    }
    #pragma unroll
    for (int x = 0; x < 32; x++) d_G[i*32 + x] = (float)(ev[x] / s);
}

// ---- channel means (float4) ----
__global__ void k_mean(const float* __restrict__ x) {
    int c = blockIdx.x, t = threadIdx.x;
    float4 v = reinterpret_cast<const float4*>(x + c*HWN)[t];
    float s = v.x + v.y + v.z + v.w;
    #pragma unroll
    for (int o = 16; o > 0; o >>= 1) s += __shfl_xor_sync(~0u, s, o);
    __shared__ float red[8];
    if ((t & 31) == 0) red[t >> 5] = s;
    __syncthreads();
    if (t == 0) {
        float tot = 0.f;
        #pragma unroll
        for (int w = 0; w < 8; w++) tot += red[w];
        d_mean[c] = tot * (1.f/1024.f);
    }
}

// ---- SE: fc -> relu -> fc -> sigmoid ----
__global__ void k_se(const float* __restrict__ w1, const float* __restrict__ w2) {
    __shared__ float s[512], s1[32];
    int t = threadIdx.x;
    s[t] = d_mean[t];
    __syncthreads();
    if (t < 32) {
        float a = 0.f;
        for (int c = 0; c < 512; c++) a += w1[t*512 + c] * s[c];
        s1[t] = fmaxf(a, 0.f);
    }
    __syncthreads();
    float a = 0.f;
    #pragma unroll
    for (int j = 0; j < 32; j++) a += w2[t*32 + j] * s1[j];
    d_scale[t] = 1.f / (1.f + expf(-a));
}

// ---- scale + sigmoid + transpose: out32[c][p], out32T[p][c], sigT[p][c] ----
__global__ void k_trans(const float* __restrict__ x) {
    int p0 = blockIdx.x * 32;   // pixel tile
    int c0 = blockIdx.y * 32;   // channel tile
    int t = threadIdx.x;
    __shared__ float V[32][33], S[32][33];
    int r = t >> 3, q = (t & 7) * 4;
    float4 xv = *reinterpret_cast<const float4*>(x + (c0 + r)*HWN + p0 + q);
    float sc = d_scale[c0 + r];
    float4 v; v.x = xv.x*sc; v.y = xv.y*sc; v.z = xv.z*sc; v.w = xv.w*sc;
    *reinterpret_cast<float4*>(d_out32 + (c0 + r)*HWN + p0 + q) = v;
    V[r][q+0] = v.x; V[r][q+1] = v.y; V[r][q+2] = v.z; V[r][q+3] = v.w;
    S[r][q+0] = 1.f/(1.f+expf(-v.x));
    S[r][q+1] = 1.f/(1.f+expf(-v.y));
    S[r][q+2] = 1.f/(1.f+expf(-v.z));
    S[r][q+3] = 1.f/(1.f+expf(-v.w));
    __syncthreads();
    // transposed write: pr = row of pixel, cq = channel quad
    int pr = t >> 3, cq = (t & 7) * 4;
    float4 ov, sv;
    ov.x = V[cq+0][pr]; ov.y = V[cq+1][pr]; ov.z = V[cq+2][pr]; ov.w = V[cq+3][pr];
    sv.x = S[cq+0][pr]; sv.y = S[cq+1][pr]; sv.z = S[cq+2][pr]; sv.w = S[cq+3][pr];
    *reinterpret_cast<float4*>(d_out32T + (p0 + pr)*512 + c0 + cq) = ov;
    *reinterpret_cast<float4*>(d_sigT   + (p0 + pr)*512 + c0 + cq) = sv;
}

// ---- gaussian stage 1: tmp[c][i*32+y] = sum_x G[i,x]*out32[c, x*32+y] ----
__global__ void k_gauss1() {
    int c = blockIdx.x, t = threadIdx.x;
    __shared__ float sO[1024], sG[1024];
    #pragma unroll
    for (int j = 0; j < 4; j++) {
        sO[t + j*256] = d_out32[c*1024 + t + j*256];
        sG[t + j*256] = d_G[t + j*256];
    }
    __syncthreads();
    #pragma unroll
    for (int j = 0; j < 4; j++) {
        int e = t + j*256;
        int i = e >> 5, y = e & 31;
        float acc = 0.f;
        #pragma unroll
        for (int xx = 0; xx < 32; xx++) acc += sG[i*32 + xx] * sO[xx*32 + y];
        d_tmp[c*1024 + e] = acc;
    }
}

// ---- gaussian stage 2 (tiled, single-read): cat[(i*32+k)*512+c] = sum_y G[k,y]*tmp[c][i*32+y]
__global__ void k_gauss2() {
    int i = blockIdx.x;          // 0..31
    int c0 = blockIdx.y * 128;   // 4 channel tiles
    int t = threadIdx.x;
    __shared__ float sm[128][33];
    __shared__ float gk[1024];
    #pragma unroll
    for (int l = t; l < 1024; l += 256) gk[l] = d_G[l];
    #pragma unroll
    for (int it = 0; it < 4; it++) {
        int s = t + it*256;           // 1024 float4 slots
        int cc = s >> 3, yq = (s & 7) * 4;
        float4 v = *reinterpret_cast<const float4*>(d_tmp + (c0+cc)*1024 + i*32 + yq);
        sm[cc][yq+0] = v.x; sm[cc][yq+1] = v.y; sm[cc][yq+2] = v.z; sm[cc][yq+3] = v.w;
    }
    __syncthreads();
    int c = t & 127, kb = t >> 7;     // kb in {0,1}
    #pragma unroll
    for (int j = 0; j < 16; j++) {
        int k = kb + j*2;
        float acc = 0.f;
        #pragma unroll
        for (int y = 0; y < 32; y++) acc += gk[k*32 + y] * sm[c][y];
        d_cat[(i*32 + k)*512 + c0 + c] = acc;
    }
}

// ---- fused CSA: score -> softmax -> apply, one block per pixel ----
__global__ void k_csa() {
    int p = blockIdx.x;
    int h = p >> 5, w = p & 31;
    int t = threadIdx.x;                 // 128 threads, channel quad t*4
    __shared__ float wred[4][9];
    __shared__ float sA[9];

    int pn[9]; bool val[9];
    #pragma unroll
    for (int di = 0; di < 3; di++)
        #pragma unroll
        for (int dj = 0; dj < 3; dj++) {
            int d = di*3 + dj;
            int gh = h + di - 1, gw = w + dj - 1;
            val[d] = (gh >= 0) & (gh < 32) & (gw >= 0) & (gw < 32);
            pn[d] = (gh*32 + gw) * 512;
        }

    float4 cen = *reinterpret_cast<const float4*>(d_sigT + p*512 + t*4);
    float part[9];
    #pragma unroll
    for (int d = 0; d < 9; d++) {
        float pd = 0.f;
        if (val[d]) {
            float4 nb = *reinterpret_cast<const float4*>(d_sigT + pn[d] + t*4);
            pd = cen.x*nb.x + cen.y*nb.y + cen.z*nb.z + cen.w*nb.w;
        }
        part[d] = pd;
    }
    int lane = t & 31, wid = t >> 5;
    #pragma unroll
    for (int d = 0; d < 9; d++) {
        float v = part[d];
        #pragma unroll
        for (int o = 16; o > 0; o >>= 1) v += __shfl_xor_sync(~0u, v, o);
        if (lane == 0) wred[wid][d] = v;
    }
    __syncthreads();
    if (t == 0) {
        float sc[9];
        #pragma unroll
        for (int d = 0; d < 9; d++)
            sc[d] = (wred[0][d] + wred[1][d] + wred[2][d] + wred[3][d]) * (1.f/512.f);
        float m = sc[0];
        #pragma unroll
        for (int d = 1; d < 9; d++) m = fmaxf(m, sc[d]);
        float e[9], ss = 0.f;
        #pragma unroll
        for (int d = 0; d < 9; d++) { e[d] = expf(sc[d] - m); ss += e[d]; }
        float inv = 1.f / ss;
        #pragma unroll
        for (int d = 0; d < 9; d++) sA[d] = e[d] * inv;
    }
    __syncthreads();

    float4 acc = make_float4(0.f, 0.f, 0.f, 0.f);
    #pragma unroll
    for (int d = 0; d < 9; d++) {
        if (val[d]) {
            float a = sA[d];
            float4 nb = *reinterpret_cast<const float4*>(d_out32T + pn[d] + t*4);
            acc.x += a*nb.x; acc.y += a*nb.y; acc.z += a*nb.z; acc.w += a*nb.w;
        }
    }
    *reinterpret_cast<float4*>(d_cat + CHW + p*512 + t*4) = acc;
}

// ---- GEMM: y[o,hw] = sum_i W[o,i]*cat_flat[i*1024+hw]  (512x1024x1024) ----
__global__ void k_gemm(const float* __restrict__ Wd) {
    int n0 = blockIdx.x * 64;
    int m0 = blockIdx.y * 64;
    int t = threadIdx.x;
    __shared__ float As[16][64];
    __shared__ float Bs[16][64];
    int tx = t & 15, ty = t >> 4;
    int ao = t >> 2,  akq = (t & 3) * 4;
    int bk = t >> 4,  bnq = (t & 15) * 4;
    const float* aptr = Wd + (m0 + ao)*1024 + akq;
    const float* bptr = d_cat + bk*1024 + n0 + bnq;
    float4 aR = *reinterpret_cast<const float4*>(aptr);
    float4 bR = *reinterpret_cast<const float4*>(bptr);
    float acc[4][4] = {};
    for (int k0 = 0; k0 < 1024; k0 += 16) {
        As[akq+0][ao] = aR.x; As[akq+1][ao] = aR.y;
        As[akq+2][ao] = aR.z; As[akq+3][ao] = aR.w;
        *reinterpret_cast<float4*>(&Bs[bk][bnq]) = bR;
        __syncthreads();
        if (k0 + 16 < 1024) {
            aR = *reinterpret_cast<const float4*>(aptr + k0 + 16);
            bR = *reinterpret_cast<const float4*>(bptr + (k0 + 16)*1024);
        }
        #pragma unroll
        for (int kk = 0; kk < 16; kk++) {
            float4 a4 = *reinterpret_cast<const float4*>(&As[kk][ty*4]);
            float4 b4 = *reinterpret_cast<const float4*>(&Bs[kk][tx*4]);
            acc[0][0] += a4.x*b4.x; acc[0][1] += a4.x*b4.y; acc[0][2] += a4.x*b4.z; acc[0][3] += a4.x*b4.w;
            acc[1][0] += a4.y*b4.x; acc[1][1] += a4.y*b4.y; acc[1][2] += a4.y*b4.z; acc[1][3] += a4.y*b4.w;
            acc[2][0] += a4.z*b4.x; acc[2][1] += a4.z*b4.y; acc[2][2] += a4.z*b4.z; acc[2][3] += a4.z*b4.w;
            acc[3][0] += a4.w*b4.x; acc[3][1] += a4.w*b4.y; acc[3][2] += a4.w*b4.z; acc[3][3] += a4.w*b4.w;
        }
        __syncthreads();
    }
    #pragma unroll
    for (int u = 0; u < 4; u++) {
        float4 o4 = make_float4(acc[u][0], acc[u][1], acc[u][2], acc[u][3]);
        *reinterpret_cast<float4*>(d_y + (m0 + ty*4 + u)*1024 + n0 + tx*4) = o4;
    }
}

// ---- instance norm (two-pass, biased var) + leaky relu(0.2) ----
__global__ void k_inorm(float* __restrict__ out) {
    int o = blockIdx.x, t = threadIdx.x;
    __shared__ float red[8];
    __shared__ float bmu, brs;
    float4 v = reinterpret_cast<const float4*>(d_y + o*1024)[t];
    float s = v.x + v.y + v.z + v.w;
    #pragma unroll
    for (int off = 16; off > 0; off >>= 1) s += __shfl_xor_sync(~0u, s, off);
    if ((t & 31) == 0) red[t >> 5] = s;
    __syncthreads();
    if (t == 0) {
        float tot = 0.f;
        #pragma unroll
        for (int w = 0; w < 8; w++) tot += red[w];
        bmu = tot * (1.f/1024.f);
    }
    __syncthreads();
    float mu = bmu;
    float dx = v.x - mu, dy = v.y - mu, dz = v.z - mu, dw = v.w - mu;
    float q = dx*dx + dy*dy + dz*dz + dw*dw;
    #pragma unroll
    for (int off = 16; off > 0; off >>= 1) q += __shfl_xor_sync(~0u, q, off);
    if ((t & 31) == 0) red[t >> 5] = q;
    __syncthreads();
    if (t == 0) {
        float tot = 0.f;
        #pragma unroll
        for (int w = 0; w < 8; w++) tot += red[w];
        brs = rsqrtf(tot * (1.f/1024.f) + 1e-5f);
    }
    __syncthreads();
    float rs = brs;
    float4 r;
    r.x = dx*rs; r.y = dy*rs; r.z = dz*rs; r.w = dw*rs;
    r.x = r.x >= 0.f ? r.x : 0.2f*r.x;
    r.y = r.y >= 0.f ? r.y : 0.2f*r.y;
    r.z = r.z >= 0.f ? r.z : 0.2f*r.z;
    r.w = r.w >= 0.f ? r.w : 0.2f*r.w;
    reinterpret_cast<float4*>(out + o*1024)[t] = r;
}

extern "C" void kernel_launch(void* const* d_in, const int* in_sizes, int n_in,
                              void* d_out, int out_size) {
    const float* x  = (const float*)d_in[0];
    const float* w1 = (const float*)d_in[1];
    const float* w2 = (const float*)d_in[2];
    const float* wd = (const float*)d_in[3];
    float* out = (float*)d_out;

    k_gauss<<<1, 32>>>();
    k_mean<<<512, 256>>>(x);
    k_se<<<1, 512>>>(w1, w2);
    k_trans<<<dim3(32, 16), 256>>>(x);
    k_gauss1<<<512, 256>>>();
    k_gauss2<<<dim3(32, 4), 256>>>();
    k_csa<<<1024, 128>>>();
    k_gemm<<<dim3(16, 8), 256>>>(wd);
    k_inorm<<<512, 256>>>(out);
}

// round 3
// speedup vs baseline: 3.5233x; 2.1846x over previous
#include <cuda_runtime.h>
#include <math.h>

#define C 512
#define HWN 1024
#define CHW (C*HWN)

__device__ __align__(16) float d_G[1024];        // G[i*32+x], normalized 1D gaussian
__device__ float d_mean[C];
__device__ float d_scale[C];
__device__ __align__(16) float d_out32[CHW];     // [c][hw]
__device__ __align__(16) float d_out32T[CHW];    // [hw][c]
__device__ __align__(16) float d_sigT[CHW];      // [hw][c]
__device__ __align__(16) float d_tmp[CHW];       // [c][i*32+y]
__device__ __align__(16) float d_cat[2*CHW];     // gus flat (p*512+c) ; csa flat
__device__ __align__(16) float d_y[CHW];

// ---- Gaussian weights: normalized separable 1D row (fp32 — ample accuracy) ----
__global__ void k_gauss() {
    int i = threadIdx.x; // 0..31
    float ev[32]; float s = 0.f;
    #pragma unroll
    for (int x = 0; x < 32; x++) {
        float dd = (float)(x - i);
        float e = expf(-dd * dd * (1.0f/4.5f));
        ev[x] = e; s += e;
    }
    float inv = 1.f / s;
    #pragma unroll
    for (int x = 0; x < 32; x++) d_G[i*32 + x] = ev[x] * inv;
}

// ---- channel means (float4) ----
__global__ void k_mean(const float* __restrict__ x) {
    int c = blockIdx.x, t = threadIdx.x;
    float4 v = reinterpret_cast<const float4*>(x + c*HWN)[t];
    float s = v.x + v.y + v.z + v.w;
    #pragma unroll
    for (int o = 16; o > 0; o >>= 1) s += __shfl_xor_sync(~0u, s, o);
    __shared__ float red[8];
    if ((t & 31) == 0) red[t >> 5] = s;
    __syncthreads();
    if (t == 0) {
        float tot = 0.f;
        #pragma unroll
        for (int w = 0; w < 8; w++) tot += red[w];
        d_mean[c] = tot * (1.f/1024.f);
    }
}

// ---- SE: fc -> relu -> fc -> sigmoid (coalesced float4 loads) ----
__global__ void k_se(const float* __restrict__ w1, const float* __restrict__ w2) {
    __shared__ float s[512], s1[32];
    int t = threadIdx.x;
    s[t] = d_mean[t];
    __syncthreads();
    // phase 1: 32 outputs, 16 lanes each, coalesced float4
    int o = t >> 4, l = t & 15;
    float a = 0.f;
    #pragma unroll
    for (int j = 0; j < 8; j++) {
        int c = (l + j*16) * 4;
        float4 w = *reinterpret_cast<const float4*>(w1 + o*512 + c);
        a += w.x*s[c] + w.y*s[c+1] + w.z*s[c+2] + w.w*s[c+3];
    }
    #pragma unroll
    for (int off = 8; off > 0; off >>= 1) a += __shfl_down_sync(~0u, a, off, 16);
    if (l == 0) s1[o] = fmaxf(a, 0.f);
    __syncthreads();
    // phase 2
    float b = 0.f;
    const float4* w2p = reinterpret_cast<const float4*>(w2 + t*32);
    #pragma unroll
    for (int j = 0; j < 8; j++) {
        float4 w = w2p[j];
        b += w.x*s1[j*4+0] + w.y*s1[j*4+1] + w.z*s1[j*4+2] + w.w*s1[j*4+3];
    }
    d_scale[t] = 1.f / (1.f + expf(-b));
}

// ---- scale + sigmoid + transpose: out32[c][p], out32T[p][c], sigT[p][c] ----
__global__ void k_trans(const float* __restrict__ x) {
    int p0 = blockIdx.x * 32;   // pixel tile
    int c0 = blockIdx.y * 32;   // channel tile
    int t = threadIdx.x;
    __shared__ float V[32][33], S[32][33];
    int r = t >> 3, q = (t & 7) * 4;
    float4 xv = *reinterpret_cast<const float4*>(x + (c0 + r)*HWN + p0 + q);
    float sc = d_scale[c0 + r];
    float4 v; v.x = xv.x*sc; v.y = xv.y*sc; v.z = xv.z*sc; v.w = xv.w*sc;
    *reinterpret_cast<float4*>(d_out32 + (c0 + r)*HWN + p0 + q) = v;
    V[r][q+0] = v.x; V[r][q+1] = v.y; V[r][q+2] = v.z; V[r][q+3] = v.w;
    S[r][q+0] = 1.f/(1.f+expf(-v.x));
    S[r][q+1] = 1.f/(1.f+expf(-v.y));
    S[r][q+2] = 1.f/(1.f+expf(-v.z));
    S[r][q+3] = 1.f/(1.f+expf(-v.w));
    __syncthreads();
    int pr = t >> 3, cq = (t & 7) * 4;
    float4 ov, sv;
    ov.x = V[cq+0][pr]; ov.y = V[cq+1][pr]; ov.z = V[cq+2][pr]; ov.w = V[cq+3][pr];
    sv.x = S[cq+0][pr]; sv.y = S[cq+1][pr]; sv.z = S[cq+2][pr]; sv.w = S[cq+3][pr];
    *reinterpret_cast<float4*>(d_out32T + (p0 + pr)*512 + c0 + cq) = ov;
    *reinterpret_cast<float4*>(d_sigT   + (p0 + pr)*512 + c0 + cq) = sv;
}

// ---- gaussian stage 1: tmp[c][i*32+y] = sum_x G[i,x]*out32[c, x*32+y] ----
__global__ void k_gauss1() {
    int c = blockIdx.x, t = threadIdx.x;
    __shared__ float sO[1024], sG[1024];
    #pragma unroll
    for (int j = 0; j < 4; j++) {
        sO[t + j*256] = d_out32[c*1024 + t + j*256];
        sG[t + j*256] = d_G[t + j*256];
    }
    __syncthreads();
    #pragma unroll
    for (int j = 0; j < 4; j++) {
        int e = t + j*256;
        int i = e >> 5, y = e & 31;
        float acc = 0.f;
        #pragma unroll
        for (int xx = 0; xx < 32; xx++) acc += sG[i*32 + xx] * sO[xx*32 + y];
        d_tmp[c*1024 + e] = acc;
    }
}

// ---- gaussian stage 2 (tiled, single-read): cat[(i*32+k)*512+c] = sum_y G[k,y]*tmp[c][i*32+y]
__global__ void k_gauss2() {
    int i = blockIdx.x;          // 0..31
    int c0 = blockIdx.y * 128;   // 4 channel tiles
    int t = threadIdx.x;
    __shared__ float sm[128][33];
    __shared__ float gk[1024];
    #pragma unroll
    for (int l = t; l < 1024; l += 256) gk[l] = d_G[l];
    #pragma unroll
    for (int it = 0; it < 4; it++) {
        int s = t + it*256;
        int cc = s >> 3, yq = (s & 7) * 4;
        float4 v = *reinterpret_cast<const float4*>(d_tmp + (c0+cc)*1024 + i*32 + yq);
        sm[cc][yq+0] = v.x; sm[cc][yq+1] = v.y; sm[cc][yq+2] = v.z; sm[cc][yq+3] = v.w;
    }
    __syncthreads();
    int c = t & 127, kb = t >> 7;
    #pragma unroll
    for (int j = 0; j < 16; j++) {
        int k = kb + j*2;
        float acc = 0.f;
        #pragma unroll
        for (int y = 0; y < 32; y++) acc += gk[k*32 + y] * sm[c][y];
        d_cat[(i*32 + k)*512 + c0 + c] = acc;
    }
}

// ---- fused CSA: score -> softmax -> apply, one block per pixel ----
__global__ void k_csa() {
    int p = blockIdx.x;
    int h = p >> 5, w = p & 31;
    int t = threadIdx.x;                 // 128 threads, channel quad t*4
    __shared__ float wred[4][9];
    __shared__ float sA[9];

    int pn[9]; bool val[9];
    #pragma unroll
    for (int di = 0; di < 3; di++)
        #pragma unroll
        for (int dj = 0; dj < 3; dj++) {
            int d = di*3 + dj;
            int gh = h + di - 1, gw = w + dj - 1;
            val[d] = (gh >= 0) & (gh < 32) & (gw >= 0) & (gw < 32);
            pn[d] = (gh*32 + gw) * 512;
        }

    float4 cen = *reinterpret_cast<const float4*>(d_sigT + p*512 + t*4);
    float part[9];
    #pragma unroll
    for (int d = 0; d < 9; d++) {
        float pd = 0.f;
        if (val[d]) {
            float4 nb = *reinterpret_cast<const float4*>(d_sigT + pn[d] + t*4);
            pd = cen.x*nb.x + cen.y*nb.y + cen.z*nb.z + cen.w*nb.w;
        }
        part[d] = pd;
    }
    int lane = t & 31, wid = t >> 5;
    #pragma unroll
    for (int d = 0; d < 9; d++) {
        float v = part[d];
        #pragma unroll
        for (int o = 16; o > 0; o >>= 1) v += __shfl_xor_sync(~0u, v, o);
        if (lane == 0) wred[wid][d] = v;
    }
    __syncthreads();
    if (t == 0) {
        float sc[9];
        #pragma unroll
        for (int d = 0; d < 9; d++)
            sc[d] = (wred[0][d] + wred[1][d] + wred[2][d] + wred[3][d]) * (1.f/512.f);
        float m = sc[0];
        #pragma unroll
        for (int d = 1; d < 9; d++) m = fmaxf(m, sc[d]);
        float e[9], ss = 0.f;
        #pragma unroll
        for (int d = 0; d < 9; d++) { e[d] = expf(sc[d] - m); ss += e[d]; }
        float inv = 1.f / ss;
        #pragma unroll
        for (int d = 0; d < 9; d++) sA[d] = e[d] * inv;
    }
    __syncthreads();

    float4 acc = make_float4(0.f, 0.f, 0.f, 0.f);
    #pragma unroll
    for (int d = 0; d < 9; d++) {
        if (val[d]) {
            float a = sA[d];
            float4 nb = *reinterpret_cast<const float4*>(d_out32T + pn[d] + t*4);
            acc.x += a*nb.x; acc.y += a*nb.y; acc.z += a*nb.z; acc.w += a*nb.w;
        }
    }
    *reinterpret_cast<float4*>(d_cat + CHW + p*512 + t*4) = acc;
}

// ---- GEMM with packed fp32x2 FMA: y[o,hw] = sum_i W[o,i]*cat[i*1024+hw] ----
__global__ void k_gemm(const float* __restrict__ Wd) {
    int n0 = blockIdx.x * 64;
    int m0 = blockIdx.y * 64;
    int t = threadIdx.x;
    __shared__ float As[16][64];
    __shared__ float Bs[16][64];
    int tx = t & 15, ty = t >> 4;
    int ao = t >> 2,  akq = (t & 3) * 4;
    int bk = t >> 4,  bnq = (t & 15) * 4;
    const float* aptr = Wd + (m0 + ao)*1024 + akq;
    const float* bptr = d_cat + bk*1024 + n0 + bnq;
    float4 aR = *reinterpret_cast<const float4*>(aptr);
    float4 bR = *reinterpret_cast<const float4*>(bptr);
    unsigned long long acc[4][2];
    #pragma unroll
    for (int u = 0; u < 4; u++) { acc[u][0] = 0ull; acc[u][1] = 0ull; }
    for (int k0 = 0; k0 < 1024; k0 += 16) {
        As[akq+0][ao] = aR.x; As[akq+1][ao] = aR.y;
        As[akq+2][ao] = aR.z; As[akq+3][ao] = aR.w;
        *reinterpret_cast<float4*>(&Bs[bk][bnq]) = bR;
        __syncthreads();
        if (k0 + 16 < 1024) {
            aR = *reinterpret_cast<const float4*>(aptr + k0 + 16);
            bR = *reinterpret_cast<const float4*>(bptr + (k0 + 16)*1024);
        }
        #pragma unroll
        for (int kk = 0; kk < 16; kk++) {
            float4 a4 = *reinterpret_cast<const float4*>(&As[kk][ty*4]);
            float4 b4 = *reinterpret_cast<const float4*>(&Bs[kk][tx*4]);
            unsigned long long b01, b23;
            asm("mov.b64 %0, {%1,%2};" : "=l"(b01) : "f"(b4.x), "f"(b4.y));
            asm("mov.b64 %0, {%1,%2};" : "=l"(b23) : "f"(b4.z), "f"(b4.w));
            float av[4] = {a4.x, a4.y, a4.z, a4.w};
            #pragma unroll
            for (int u = 0; u < 4; u++) {
                unsigned long long aa;
                asm("mov.b64 %0, {%1,%1};" : "=l"(aa) : "f"(av[u]));
                asm("fma.rn.f32x2 %0, %1, %2, %0;" : "+l"(acc[u][0]) : "l"(aa), "l"(b01));
                asm("fma.rn.f32x2 %0, %1, %2, %0;" : "+l"(acc[u][1]) : "l"(aa), "l"(b23));
            }
        }
        __syncthreads();
    }
    #pragma unroll
    for (int u = 0; u < 4; u++) {
        float4 o4;
        asm("mov.b64 {%0,%1}, %2;" : "=f"(o4.x), "=f"(o4.y) : "l"(acc[u][0]));
        asm("mov.b64 {%0,%1}, %2;" : "=f"(o4.z), "=f"(o4.w) : "l"(acc[u][1]));
        *reinterpret_cast<float4*>(d_y + (m0 + ty*4 + u)*1024 + n0 + tx*4) = o4;
    }
}

// ---- instance norm (two-pass, biased var) + leaky relu(0.2) ----
__global__ void k_inorm(float* __restrict__ out) {
    int o = blockIdx.x, t = threadIdx.x;
    __shared__ float red[8];
    __shared__ float bmu, brs;
    float4 v = reinterpret_cast<const float4*>(d_y + o*1024)[t];
    float s = v.x + v.y + v.z + v.w;
    #pragma unroll
    for (int off = 16; off > 0; off >>= 1) s += __shfl_xor_sync(~0u, s, off);
    if ((t & 31) == 0) red[t >> 5] = s;
    __syncthreads();
    if (t == 0) {
        float tot = 0.f;
        #pragma unroll
        for (int w = 0; w < 8; w++) tot += red[w];
        bmu = tot * (1.f/1024.f);
    }
    __syncthreads();
    float mu = bmu;
    float dx = v.x - mu, dy = v.y - mu, dz = v.z - mu, dw = v.w - mu;
    float q = dx*dx + dy*dy + dz*dz + dw*dw;
    #pragma unroll
    for (int off = 16; off > 0; off >>= 1) q += __shfl_xor_sync(~0u, q, off);
    if ((t & 31) == 0) red[t >> 5] = q;
    __syncthreads();
    if (t == 0) {
        float tot = 0.f;
        #pragma unroll
        for (int w = 0; w < 8; w++) tot += red[w];
        brs = rsqrtf(tot * (1.f/1024.f) + 1e-5f);
    }
    __syncthreads();
    float rs = brs;
    float4 r;
    r.x = dx*rs; r.y = dy*rs; r.z = dz*rs; r.w = dw*rs;
    r.x = r.x >= 0.f ? r.x : 0.2f*r.x;
    r.y = r.y >= 0.f ? r.y : 0.2f*r.y;
    r.z = r.z >= 0.f ? r.z : 0.2f*r.z;
    r.w = r.w >= 0.f ? r.w : 0.2f*r.w;
    reinterpret_cast<float4*>(out + o*1024)[t] = r;
}

extern "C" void kernel_launch(void* const* d_in, const int* in_sizes, int n_in,
                              void* d_out, int out_size) {
    const float* x  = (const float*)d_in[0];
    const float* w1 = (const float*)d_in[1];
    const float* w2 = (const float*)d_in[2];
    const float* wd = (const float*)d_in[3];
    float* out = (float*)d_out;

    k_gauss<<<1, 32>>>();
    k_mean<<<512, 256>>>(x);
    k_se<<<1, 512>>>(w1, w2);
    k_trans<<<dim3(32, 16), 256>>>(x);
    k_gauss1<<<512, 256>>>();
    k_gauss2<<<dim3(32, 4), 256>>>();
    k_csa<<<1024, 128>>>();
    k_gemm<<<dim3(16, 8), 256>>>(wd);
    k_inorm<<<512, 256>>>(out);
}